// round 4
// baseline (speedup 1.0000x reference)
#include <cuda_runtime.h>
#include <cstdint>
#include <stddef.h>
#include <math.h>

#define NLEV 24
#define CAPACITY (1u << 18)
#define BLOCK 128

// ---------------- constant-bank weight storage ----------------
struct CW {
    float2 w1[51 * 16];    // layer1 weights, row-major pairs
    float2 w2[32 * 16];
    float2 w3[32 * 16];
    float2 w4g[32 * 16];   // layer4 geom cols 1..32, row-major pairs
    float  w4s[32];        // layer4 sdf col 0
    float2 b1[16];
    float2 b2[16];
    float2 b3[16];
    float  b4[33];
};
__constant__ CW cw;
__device__ CW g_stage;     // device staging buffer (packed by pack_kernel)

__global__ void pack_kernel(const float* __restrict__ w1, const float* __restrict__ b1,
                            const float* __restrict__ w2, const float* __restrict__ b2,
                            const float* __restrict__ w3, const float* __restrict__ b3,
                            const float* __restrict__ w4, const float* __restrict__ b4)
{
    const int t = blockIdx.x * blockDim.x + threadIdx.x;
    const int stride = gridDim.x * blockDim.x;
    float* dst = (float*)&g_stage;

    const int OW1  = (int)(offsetof(CW, w1)  / 4);
    const int OW2  = (int)(offsetof(CW, w2)  / 4);
    const int OW3  = (int)(offsetof(CW, w3)  / 4);
    const int OW4G = (int)(offsetof(CW, w4g) / 4);
    const int OW4S = (int)(offsetof(CW, w4s) / 4);
    const int OB1  = (int)(offsetof(CW, b1)  / 4);
    const int OB2  = (int)(offsetof(CW, b2)  / 4);
    const int OB3  = (int)(offsetof(CW, b3)  / 4);
    const int OB4  = (int)(offsetof(CW, b4)  / 4);

    for (int i = t; i < 51 * 32; i += stride) dst[OW1 + i] = w1[i];
    for (int i = t; i < 32 * 32; i += stride) dst[OW2 + i] = w2[i];
    for (int i = t; i < 32 * 32; i += stride) dst[OW3 + i] = w3[i];
    for (int i = t; i < 32 * 33; i += stride) {
        const int r = i / 33, c = i - r * 33;
        const float v = w4[i];
        if (c == 0) dst[OW4S + r] = v;
        else        dst[OW4G + r * 32 + (c - 1)] = v;
    }
    for (int i = t; i < 32; i += stride) { dst[OB1 + i] = b1[i]; dst[OB2 + i] = b2[i]; dst[OB3 + i] = b3[i]; }
    for (int i = t; i < 33; i += stride) dst[OB4 + i] = b4[i];
}

// ---------------- math helpers ----------------
union F2U { float2 f; unsigned long long u; };

__device__ __forceinline__ float2 ffma2(float2 a, float2 b, float2 c) {
    F2U A, B, C, D;
    A.f = a; B.f = b; C.f = c;
    asm("fma.rn.f32x2 %0, %1, %2, %3;" : "=l"(D.u) : "l"(A.u), "l"(B.u), "l"(C.u));
    return D.f;
}
__device__ __forceinline__ float2 f2(float a, float b) { return make_float2(a, b); }

// Branch-free exact-GELU via Abramowitz-Stegun 7.1.26 erf (|err| <= ~1.5e-7 abs).
__device__ __forceinline__ float gelu_fast(float v) {
    const float z  = v * 0.70710678118654752f;
    const float az = fabsf(z);
    const float t  = __fdividef(1.0f, fmaf(0.3275911f, az, 1.0f));
    float p = fmaf(1.061405429f, t, -1.453152027f);
    p = fmaf(p, t, 1.421413741f);
    p = fmaf(p, t, -0.284496736f);
    p = fmaf(p, t, 0.254829592f);
    p *= t;
    const float e  = __expf(-az * az);
    const float er = copysignf(fmaf(-p, e, 1.0f), z);
    return 0.5f * v * (1.0f + er);
}

// Compute one level's lattice weights (c2f window folded in) and ISSUE the 4
// hash gathers. Results consumed later (software pipeline).
__device__ __forceinline__ void level_setup(
    int lev, float p0, float p1, float p2,
    const float* __restrict__ s_invsc,
    const float* __restrict__ s_shift,
    const float* __restrict__ s_win,
    const float2* __restrict__ tables,
    float2 g[4], float wgt[4])
{
    const float SF0 = 2.30940107675850341796875f;  // 4*sqrt(2/3)/sqrt(1*2)
    const float SF1 = 1.33333333333333333f;
    const float SF2 = 0.94280904158206336f;

    const float inv  = s_invsc[lev];
    const float pos0 = fmaf(p0, inv, s_shift[lev * 3 + 0]);
    const float pos1 = fmaf(p1, inv, s_shift[lev * 3 + 1]);
    const float pos2 = fmaf(p2, inv, s_shift[lev * 3 + 2]);
    const float cf0 = pos0 * SF0, cf1 = pos1 * SF1, cf2 = pos2 * SF2;

    const float S2 = cf2;
    const float S1 = cf2 + cf1;
    const float S0 = S1 + cf0;

    float e[4];
    e[0] = S0;
    e[1] = S1 - cf0;
    e[2] = S2 - 2.0f * cf1;
    e[3] = -3.0f * cf2;

    float r[4];
    #pragma unroll
    for (int i = 0; i < 4; i++) r[i] = rintf(e[i] * 0.25f) * 4.0f;

    const int sumv = (int)rintf((r[0] + r[1] + r[2] + r[3]) * 0.25f);

    float d[4];
    #pragma unroll
    for (int i = 0; i < 4; i++) d[i] = e[i] - r[i];

    // rank = stable argsort(argsort(-diff)) + sum_
    int rk[4];
    #pragma unroll
    for (int i = 0; i < 4; i++) {
        int c = sumv;
        #pragma unroll
        for (int j = 0; j < 4; j++)
            c += (d[j] > d[i] || (d[j] == d[i] && j < i)) ? 1 : 0;
        rk[i] = c;
    }
    #pragma unroll
    for (int i = 0; i < 4; i++) {
        if (rk[i] < 0)      { rk[i] += 4; r[i] += 4.0f; }
        else if (rk[i] > 3) { rk[i] -= 4; r[i] -= 4.0f; }
    }

    float del[4];
    #pragma unroll
    for (int i = 0; i < 4; i++) del[i] = (e[i] - r[i]) * 0.25f;

    float bq0 = 0.f, bq1 = 0.f, bq2 = 0.f, bq3 = 0.f, bq4 = 0.f;
    #pragma unroll
    for (int i = 0; i < 4; i++) {
        const int id = 3 - rk[i];
        const float dv = del[i];
        if (id == 0)      { bq0 += dv; bq1 -= dv; }
        else if (id == 1) { bq1 += dv; bq2 -= dv; }
        else if (id == 2) { bq2 += dv; bq3 -= dv; }
        else              { bq3 += dv; bq4 -= dv; }
    }
    const float wl = s_win[lev];
    wgt[0] = (bq0 + 1.0f + bq4) * wl;
    wgt[1] = bq1 * wl;
    wgt[2] = bq2 * wl;
    wgt[3] = bq3 * wl;

    const int c0 = (int)r[0], c1 = (int)r[1], c2 = (int)r[2];
    const float2* tab = tables + (size_t)lev * CAPACITY;

    #pragma unroll
    for (int k = 0; k < 4; k++) {
        const uint32_t k0 = (uint32_t)(c0 + k - ((rk[0] > 3 - k) ? 4 : 0));
        const uint32_t k1 = (uint32_t)(c1 + k - ((rk[1] > 3 - k) ? 4 : 0));
        const uint32_t k2 = (uint32_t)(c2 + k - ((rk[2] > 3 - k) ? 4 : 0));
        const uint32_t h = k0 ^ (k1 * 2654435761u) ^ (k2 * 805459861u);
        g[k] = __ldg(tab + (h & (CAPACITY - 1u)));
    }
}

__global__ __launch_bounds__(BLOCK, 4)
void sdf_kernel(const float* __restrict__ points,
                const int*   __restrict__ iter_nr,
                const float* __restrict__ tables,
                const float* __restrict__ shifts,
                float* __restrict__ out, int N)
{
    __shared__ float s_shift[NLEV * 3];
    __shared__ float s_invsc[NLEV];
    __shared__ float s_win[NLEV];
    __shared__ int   s_nlev;
    __shared__ float s_stage[BLOCK * 33];  // geom staging (stride 33: conflict-free)

    const int tid = threadIdx.x;

    if (tid < NLEV * 3) s_shift[tid] = shifts[tid];
    if (tid < NLEV) {
        // SCALES = geomspace(1, 1e-4, 24) = 10^(i * (-4/23)) in float64 -> f32
        double step = -4.0 / 23.0;
        float sc = (float)pow(10.0, step * (double)tid);
        s_invsc[tid] = 1.0f / sc;
        float t = fminf(fmaxf((float)iter_nr[0] / 10000.0f, 0.0f), 1.0f);
        float alpha = (0.3f + 0.7f * t) * (float)NLEV;
        float x = fminf(fmaxf(alpha - (float)tid, 0.0f), 1.0f);
        s_win[tid] = 0.5f * (1.0f - cosf(3.14159265358979323846f * x));
        if (tid == 0) {
            int na = (int)ceilf(alpha);
            if (na > NLEV) na = NLEV;
            if (na < 0) na = 0;
            s_nlev = na;
        }
    }
    __syncthreads();

    const int n = blockIdx.x * BLOCK + tid;
    const bool active = (n < N);
    const int nlev = s_nlev;

    float  acc0;        // sdf
    float2 accg[16];    // geom 1..32

    if (active) {
        const float p0 = __ldg(points + n * 3 + 0);
        const float p1 = __ldg(points + n * 3 + 1);
        const float p2 = __ldg(points + n * 3 + 2);
        const float2* tab2 = (const float2*)tables;

        // ---- layer-1 accumulator, seeded with bias + point*0.001 rows (48..50)
        float2 h1[16];
        {
            const float2 xa = f2(p0 * 0.001f, p0 * 0.001f);
            const float2 xb = f2(p1 * 0.001f, p1 * 0.001f);
            const float2 xc = f2(p2 * 0.001f, p2 * 0.001f);
            #pragma unroll
            for (int q = 0; q < 16; q++) {
                float2 v = ffma2(xa, cw.w1[48 * 16 + q], cw.b1[q]);
                v = ffma2(xb, cw.w1[49 * 16 + q], v);
                h1[q] = ffma2(xc, cw.w1[50 * 16 + q], v);
            }
        }

        // ---- permutohedral encoding: software-pipelined gathers ----
        float2 g[4]; float wg[4];
        if (nlev > 0)
            level_setup(0, p0, p1, p2, s_invsc, s_shift, s_win, tab2, g, wg);

        #pragma unroll 1
        for (int lev = 0; lev < nlev; ++lev) {
            float2 gn[4]; float wn[4];
            if (lev + 1 < nlev)
                level_setup(lev + 1, p0, p1, p2, s_invsc, s_shift, s_win, tab2, gn, wn);

            float2 fe = f2(0.0f, 0.0f);
            #pragma unroll
            for (int k = 0; k < 4; k++)
                fe = ffma2(f2(wg[k], wg[k]), g[k], fe);

            const float2 f02 = f2(fe.x, fe.x);
            const float2 f12 = f2(fe.y, fe.y);

            const int ra = (2 * lev) * 16;
            #pragma unroll
            for (int q = 0; q < 16; q++) {
                float2 v = ffma2(f02, cw.w1[ra + q], h1[q]);
                h1[q] = ffma2(f12, cw.w1[ra + 16 + q], v);
            }

            #pragma unroll
            for (int k = 0; k < 4; k++) { g[k] = gn[k]; wg[k] = wn[k]; }
        }

        // ---- MLP ----
        #pragma unroll
        for (int q = 0; q < 16; q++) {
            h1[q].x = gelu_fast(h1[q].x);
            h1[q].y = gelu_fast(h1[q].y);
        }

        float2 h2[16];
        #pragma unroll
        for (int q = 0; q < 16; q++) h2[q] = cw.b2[q];
        #pragma unroll
        for (int i = 0; i < 16; i++) {
            const float2 xa = f2(h1[i].x, h1[i].x);
            const float2 xb = f2(h1[i].y, h1[i].y);
            #pragma unroll
            for (int q = 0; q < 16; q++) {
                float2 v = ffma2(xa, cw.w2[(2 * i) * 16 + q], h2[q]);
                h2[q] = ffma2(xb, cw.w2[(2 * i + 1) * 16 + q], v);
            }
        }
        #pragma unroll
        for (int q = 0; q < 16; q++) {
            h2[q].x = gelu_fast(h2[q].x);
            h2[q].y = gelu_fast(h2[q].y);
        }

        #pragma unroll
        for (int q = 0; q < 16; q++) h1[q] = cw.b3[q];
        #pragma unroll
        for (int i = 0; i < 16; i++) {
            const float2 xa = f2(h2[i].x, h2[i].x);
            const float2 xb = f2(h2[i].y, h2[i].y);
            #pragma unroll
            for (int q = 0; q < 16; q++) {
                float2 v = ffma2(xa, cw.w3[(2 * i) * 16 + q], h1[q]);
                h1[q] = ffma2(xb, cw.w3[(2 * i + 1) * 16 + q], v);
            }
        }
        #pragma unroll
        for (int q = 0; q < 16; q++) {
            h1[q].x = gelu_fast(h1[q].x);
            h1[q].y = gelu_fast(h1[q].y);
        }

        // layer 4
        acc0 = cw.b4[0];
        #pragma unroll
        for (int q = 0; q < 16; q++)
            accg[q] = f2(cw.b4[1 + 2 * q], cw.b4[2 + 2 * q]);
        #pragma unroll
        for (int i = 0; i < 16; i++) {
            const float x0 = h1[i].x, x1 = h1[i].y;
            const float2 xa = f2(x0, x0);
            const float2 xb = f2(x1, x1);
            acc0 = fmaf(x0, cw.w4s[2 * i], acc0);
            acc0 = fmaf(x1, cw.w4s[2 * i + 1], acc0);
            #pragma unroll
            for (int q = 0; q < 16; q++) {
                float2 v = ffma2(xa, cw.w4g[(2 * i) * 16 + q], accg[q]);
                accg[q] = ffma2(xb, cw.w4g[(2 * i + 1) * 16 + q], v);
            }
        }

        // sdf (coalesced across warp)
        out[n] = acc0;

        #pragma unroll
        for (int q = 0; q < 16; q++) {
            s_stage[tid * 33 + 2 * q]     = accg[q].x;
            s_stage[tid * 33 + 2 * q + 1] = accg[q].y;
        }
    }

    __syncthreads();

    // coalesced geom writeback
    const int blockBase = blockIdx.x * BLOCK;
    int nvalid = N - blockBase;
    if (nvalid > BLOCK) nvalid = BLOCK;
    if (nvalid > 0) {
        float* gout = out + (size_t)N + (size_t)blockBase * 32;
        for (int i = tid; i < nvalid * 32; i += BLOCK) {
            const int row = i >> 5;
            const int col = i & 31;
            gout[i] = s_stage[row * 33 + col];
        }
    }
}

extern "C" void kernel_launch(void* const* d_in, const int* in_sizes, int n_in,
                              void* d_out, int out_size)
{
    const float* points = (const float*)d_in[0];
    const int*   iter   = (const int*)  d_in[1];
    const float* tables = (const float*)d_in[2];
    const float* shifts = (const float*)d_in[3];
    const float* w1 = (const float*)d_in[4];  const float* b1 = (const float*)d_in[5];
    const float* w2 = (const float*)d_in[6];  const float* b2 = (const float*)d_in[7];
    const float* w3 = (const float*)d_in[8];  const float* b3 = (const float*)d_in[9];
    const float* w4 = (const float*)d_in[10]; const float* b4 = (const float*)d_in[11];

    // 1) pack weights into device staging buffer
    pack_kernel<<<8, 256>>>(w1, b1, w2, b2, w3, b3, w4, b4);

    // 2) single D2D copy into the constant bank (graph-capturable memcpy node)
    void* stage_ptr = nullptr;
    cudaGetSymbolAddress(&stage_ptr, g_stage);
    cudaMemcpyToSymbolAsync(cw, stage_ptr, sizeof(CW), 0, cudaMemcpyDeviceToDevice, 0);

    // 3) main kernel
    const int N = in_sizes[0] / 3;
    const int grid = (N + BLOCK - 1) / BLOCK;
    sdf_kernel<<<grid, BLOCK>>>(points, iter, tables, shifts, (float*)d_out, N);
}

// round 5
// speedup vs baseline: 1.0328x; 1.0328x over previous
#include <cuda_runtime.h>
#include <cstdint>
#include <math.h>

#define NLEV 24
#define CAPACITY (1u << 18)
#define BLOCK 128

union F2U { float2 f; unsigned long long u; };

// Packed dual-lane FMA: d = a*b + c on both f32 lanes (Blackwell FFMA2).
__device__ __forceinline__ float2 ffma2(float2 a, float2 b, float2 c) {
    F2U A, B, C, D;
    A.f = a; B.f = b; C.f = c;
    asm("fma.rn.f32x2 %0, %1, %2, %3;" : "=l"(D.u) : "l"(A.u), "l"(B.u), "l"(C.u));
    return D.f;
}
__device__ __forceinline__ float2 f2(float a, float b) { return make_float2(a, b); }

// Branch-free exact-GELU via Abramowitz-Stegun 7.1.26 erf (|err| <= ~1.5e-7 abs).
__device__ __forceinline__ float gelu_fast(float v) {
    const float z  = v * 0.70710678118654752f;
    const float az = fabsf(z);
    const float t  = __fdividef(1.0f, fmaf(0.3275911f, az, 1.0f));
    float p = fmaf(1.061405429f, t, -1.453152027f);
    p = fmaf(p, t, 1.421413741f);
    p = fmaf(p, t, -0.284496736f);
    p = fmaf(p, t, 0.254829592f);
    p *= t;
    const float e  = __expf(-az * az);
    const float er = copysignf(fmaf(-p, e, 1.0f), z);
    return 0.5f * v * (1.0f + er);
}

// Compute one level's lattice weights (c2f window folded in) and ISSUE the 4
// hash gathers. Results consumed later (software pipeline).
__device__ __forceinline__ void level_setup(
    int lev, float p0, float p1, float p2,
    const float* __restrict__ s_invsc,
    const float* __restrict__ s_shift,
    const float* __restrict__ s_win,
    const float2* __restrict__ tables,
    float2 g[4], float wgt[4])
{
    const float SF0 = 2.30940107675850341796875f;  // 4*sqrt(2/3)/sqrt(1*2)
    const float SF1 = 1.33333333333333333f;
    const float SF2 = 0.94280904158206336f;

    const float inv  = s_invsc[lev];
    const float pos0 = fmaf(p0, inv, s_shift[lev * 3 + 0]);
    const float pos1 = fmaf(p1, inv, s_shift[lev * 3 + 1]);
    const float pos2 = fmaf(p2, inv, s_shift[lev * 3 + 2]);
    const float cf0 = pos0 * SF0, cf1 = pos1 * SF1, cf2 = pos2 * SF2;

    const float S2 = cf2;
    const float S1 = cf2 + cf1;
    const float S0 = S1 + cf0;

    float e[4];
    e[0] = S0;
    e[1] = S1 - cf0;
    e[2] = S2 - 2.0f * cf1;
    e[3] = -3.0f * cf2;

    float r[4];
    #pragma unroll
    for (int i = 0; i < 4; i++) r[i] = rintf(e[i] * 0.25f) * 4.0f;

    const int sumv = (int)rintf((r[0] + r[1] + r[2] + r[3]) * 0.25f);

    float d[4];
    #pragma unroll
    for (int i = 0; i < 4; i++) d[i] = e[i] - r[i];

    // rank = stable argsort(argsort(-diff)) + sum_
    int rk[4];
    #pragma unroll
    for (int i = 0; i < 4; i++) {
        int c = sumv;
        #pragma unroll
        for (int j = 0; j < 4; j++)
            c += (d[j] > d[i] || (d[j] == d[i] && j < i)) ? 1 : 0;
        rk[i] = c;
    }
    #pragma unroll
    for (int i = 0; i < 4; i++) {
        if (rk[i] < 0)      { rk[i] += 4; r[i] += 4.0f; }
        else if (rk[i] > 3) { rk[i] -= 4; r[i] -= 4.0f; }
    }

    float del[4];
    #pragma unroll
    for (int i = 0; i < 4; i++) del[i] = (e[i] - r[i]) * 0.25f;

    // barycentric weights
    float bq0 = 0.f, bq1 = 0.f, bq2 = 0.f, bq3 = 0.f, bq4 = 0.f;
    #pragma unroll
    for (int i = 0; i < 4; i++) {
        const int id = 3 - rk[i];
        const float dv = del[i];
        if (id == 0)      { bq0 += dv; bq1 -= dv; }
        else if (id == 1) { bq1 += dv; bq2 -= dv; }
        else if (id == 2) { bq2 += dv; bq3 -= dv; }
        else              { bq3 += dv; bq4 -= dv; }
    }
    const float wl = s_win[lev];   // fold window into the weights
    wgt[0] = (bq0 + 1.0f + bq4) * wl;
    wgt[1] = bq1 * wl;
    wgt[2] = bq2 * wl;
    wgt[3] = bq3 * wl;

    const int c0 = (int)r[0], c1 = (int)r[1], c2 = (int)r[2];
    const float2* tab = tables + (size_t)lev * CAPACITY;

    #pragma unroll
    for (int k = 0; k < 4; k++) {
        const uint32_t k0 = (uint32_t)(c0 + k - ((rk[0] > 3 - k) ? 4 : 0));
        const uint32_t k1 = (uint32_t)(c1 + k - ((rk[1] > 3 - k) ? 4 : 0));
        const uint32_t k2 = (uint32_t)(c2 + k - ((rk[2] > 3 - k) ? 4 : 0));
        const uint32_t h = k0 ^ (k1 * 2654435761u) ^ (k2 * 805459861u);
        g[k] = __ldg(tab + (h & (CAPACITY - 1u)));
    }
}

__global__ __launch_bounds__(BLOCK, 5)
void sdf_kernel(const float* __restrict__ points,
                const int*   __restrict__ iter_nr,
                const float* __restrict__ tables,
                const float* __restrict__ shifts,
                const float* __restrict__ w1, const float* __restrict__ b1,
                const float* __restrict__ w2, const float* __restrict__ b2,
                const float* __restrict__ w3, const float* __restrict__ b3,
                const float* __restrict__ w4, const float* __restrict__ b4,
                float* __restrict__ out, int N)
{
    __shared__ float4 s_w1[51 * 8];
    __shared__ float4 s_w2[32 * 8];
    __shared__ float4 s_w3[32 * 8];
    __shared__ float4 s_w4g[32 * 8];    // geom cols 1..32, row stride 8xfloat4
    __shared__ float  s_w4s[32];        // sdf column 0
    __shared__ float2 s_b1[16];
    __shared__ float2 s_b2[16];
    __shared__ float2 s_b3[16];
    __shared__ float  s_b4[33];
    __shared__ float  s_shift[NLEV * 3];
    __shared__ float  s_invsc[NLEV];
    __shared__ float  s_win[NLEV];
    __shared__ int    s_nlev;
    __shared__ float  s_stage[BLOCK * 33]; // geom staging (stride 33: conflict-free)

    const int tid = threadIdx.x;

    // ---- cooperative shared load of weights / constants ----
    {
        const float4* g1 = (const float4*)w1;
        const float4* g2 = (const float4*)w2;
        const float4* g3 = (const float4*)w3;
        for (int i = tid; i < 51 * 8; i += BLOCK) s_w1[i] = g1[i];
        for (int i = tid; i < 32 * 8; i += BLOCK) s_w2[i] = g2[i];
        for (int i = tid; i < 32 * 8; i += BLOCK) s_w3[i] = g3[i];
    }
    {
        float* w4g = (float*)s_w4g;
        for (int i = tid; i < 32 * 33; i += BLOCK) {
            int r = i / 33, c = i - r * 33;
            float v = w4[i];
            if (c == 0) s_w4s[r] = v; else w4g[r * 32 + (c - 1)] = v;
        }
    }
    if (tid < 16) {
        s_b1[tid] = ((const float2*)b1)[tid];
        s_b2[tid] = ((const float2*)b2)[tid];
        s_b3[tid] = ((const float2*)b3)[tid];
    }
    if (tid < 33) s_b4[tid] = b4[tid];
    if (tid < NLEV * 3) s_shift[tid] = shifts[tid];
    if (tid < NLEV) {
        // SCALES = geomspace(1, 1e-4, 24) = 10^(i * (-4/23)) in float64 -> f32
        double step = -4.0 / 23.0;
        float sc = (float)pow(10.0, step * (double)tid);
        s_invsc[tid] = 1.0f / sc;
        float t = fminf(fmaxf((float)iter_nr[0] / 10000.0f, 0.0f), 1.0f);
        float alpha = (0.3f + 0.7f * t) * (float)NLEV;
        float x = fminf(fmaxf(alpha - (float)tid, 0.0f), 1.0f);
        s_win[tid] = 0.5f * (1.0f - cosf(3.14159265358979323846f * x));
        if (tid == 0) {
            int na = (int)ceilf(alpha);
            if (na > NLEV) na = NLEV;
            if (na < 0) na = 0;
            s_nlev = na;
        }
    }
    __syncthreads();

    const int n = blockIdx.x * BLOCK + tid;
    const bool active = (n < N);
    const int nlev = s_nlev;

    float  acc0;        // sdf
    float2 accg[16];    // geom 1..32

    if (active) {
        const float p0 = __ldg(points + n * 3 + 0);
        const float p1 = __ldg(points + n * 3 + 1);
        const float p2 = __ldg(points + n * 3 + 2);
        const float2* tab2 = (const float2*)tables;

        // ---- layer-1 accumulator, seeded with bias + point*0.001 rows (48..50)
        float2 h1[16];
        {
            const float2 xa = f2(p0 * 0.001f, p0 * 0.001f);
            const float2 xb = f2(p1 * 0.001f, p1 * 0.001f);
            const float2 xc = f2(p2 * 0.001f, p2 * 0.001f);
            const float4* wa = s_w1 + 48 * 8;
            const float4* wb = s_w1 + 49 * 8;
            const float4* wc = s_w1 + 50 * 8;
            #pragma unroll
            for (int q = 0; q < 8; q++) {
                float4 A = wa[q], B = wb[q], C = wc[q];
                float2 v0 = ffma2(xa, f2(A.x, A.y), s_b1[2*q]);
                v0 = ffma2(xb, f2(B.x, B.y), v0);
                h1[2*q] = ffma2(xc, f2(C.x, C.y), v0);
                float2 v1 = ffma2(xa, f2(A.z, A.w), s_b1[2*q+1]);
                v1 = ffma2(xb, f2(B.z, B.w), v1);
                h1[2*q+1] = ffma2(xc, f2(C.z, C.w), v1);
            }
        }

        // ---- permutohedral encoding: software-pipelined gathers ----
        float2 g[4]; float wg[4];
        if (nlev > 0)
            level_setup(0, p0, p1, p2, s_invsc, s_shift, s_win, tab2, g, wg);

        #pragma unroll 1
        for (int lev = 0; lev < nlev; ++lev) {
            float2 gn[4]; float wn[4];
            if (lev + 1 < nlev)
                level_setup(lev + 1, p0, p1, p2, s_invsc, s_shift, s_win, tab2, gn, wn);

            // consume current level's gathers
            float2 fe = f2(0.0f, 0.0f);
            #pragma unroll
            for (int k = 0; k < 4; k++)
                fe = ffma2(f2(wg[k], wg[k]), g[k], fe);

            const float2 f02 = f2(fe.x, fe.x);
            const float2 f12 = f2(fe.y, fe.y);

            // accumulate into layer-1 hidden: rows 2*lev, 2*lev+1 of w1
            const float4* ra = s_w1 + (2 * lev) * 8;
            #pragma unroll
            for (int q = 0; q < 8; q++) {
                float4 A = ra[q];       // row 2*lev
                float4 B = ra[q + 8];   // row 2*lev+1
                float2 v0 = ffma2(f02, f2(A.x, A.y), h1[2*q]);
                h1[2*q] = ffma2(f12, f2(B.x, B.y), v0);
                float2 v1 = ffma2(f02, f2(A.z, A.w), h1[2*q+1]);
                h1[2*q+1] = ffma2(f12, f2(B.z, B.w), v1);
            }

            #pragma unroll
            for (int k = 0; k < 4; k++) { g[k] = gn[k]; wg[k] = wn[k]; }
        }

        // ---- MLP ----
        #pragma unroll
        for (int q = 0; q < 16; q++) {
            h1[q].x = gelu_fast(h1[q].x);
            h1[q].y = gelu_fast(h1[q].y);
        }

        float2 h2[16];
        #pragma unroll
        for (int q = 0; q < 16; q++) h2[q] = s_b2[q];
        #pragma unroll
        for (int i = 0; i < 16; i++) {
            const float x0 = h1[i].x, x1 = h1[i].y;
            const float2 xa = f2(x0, x0);
            const float2 xb = f2(x1, x1);
            const float4* wr0 = s_w2 + (2 * i) * 8;
            const float4* wr1 = wr0 + 8;
            #pragma unroll
            for (int q = 0; q < 8; q++) {
                float4 A = wr0[q], B = wr1[q];
                float2 v0 = ffma2(xa, f2(A.x, A.y), h2[2*q]);
                h2[2*q] = ffma2(xb, f2(B.x, B.y), v0);
                float2 v1 = ffma2(xa, f2(A.z, A.w), h2[2*q+1]);
                h2[2*q+1] = ffma2(xb, f2(B.z, B.w), v1);
            }
        }
        #pragma unroll
        for (int q = 0; q < 16; q++) {
            h2[q].x = gelu_fast(h2[q].x);
            h2[q].y = gelu_fast(h2[q].y);
        }

        // layer 3 back into h1
        #pragma unroll
        for (int q = 0; q < 16; q++) h1[q] = s_b3[q];
        #pragma unroll
        for (int i = 0; i < 16; i++) {
            const float x0 = h2[i].x, x1 = h2[i].y;
            const float2 xa = f2(x0, x0);
            const float2 xb = f2(x1, x1);
            const float4* wr0 = s_w3 + (2 * i) * 8;
            const float4* wr1 = wr0 + 8;
            #pragma unroll
            for (int q = 0; q < 8; q++) {
                float4 A = wr0[q], B = wr1[q];
                float2 v0 = ffma2(xa, f2(A.x, A.y), h1[2*q]);
                h1[2*q] = ffma2(xb, f2(B.x, B.y), v0);
                float2 v1 = ffma2(xa, f2(A.z, A.w), h1[2*q+1]);
                h1[2*q+1] = ffma2(xb, f2(B.z, B.w), v1);
            }
        }
        #pragma unroll
        for (int q = 0; q < 16; q++) {
            h1[q].x = gelu_fast(h1[q].x);
            h1[q].y = gelu_fast(h1[q].y);
        }

        // layer 4
        acc0 = s_b4[0];
        #pragma unroll
        for (int q = 0; q < 16; q++)
            accg[q] = f2(s_b4[1 + 2 * q], s_b4[2 + 2 * q]);
        #pragma unroll
        for (int i = 0; i < 16; i++) {
            const float x0 = h1[i].x, x1 = h1[i].y;
            const float2 xa = f2(x0, x0);
            const float2 xb = f2(x1, x1);
            const float4* wr0 = s_w4g + (2 * i) * 8;
            const float4* wr1 = wr0 + 8;
            acc0 = fmaf(x0, s_w4s[2 * i], acc0);
            acc0 = fmaf(x1, s_w4s[2 * i + 1], acc0);
            #pragma unroll
            for (int q = 0; q < 8; q++) {
                float4 A = wr0[q], B = wr1[q];
                float2 v0 = ffma2(xa, f2(A.x, A.y), accg[2*q]);
                accg[2*q] = ffma2(xb, f2(B.x, B.y), v0);
                float2 v1 = ffma2(xa, f2(A.z, A.w), accg[2*q+1]);
                accg[2*q+1] = ffma2(xb, f2(B.z, B.w), v1);
            }
        }

        // sdf (coalesced across warp)
        out[n] = acc0;

        // stage geom in smem for coalesced write (stride 33: conflict-free)
        #pragma unroll
        for (int q = 0; q < 16; q++) {
            s_stage[tid * 33 + 2 * q]     = accg[q].x;
            s_stage[tid * 33 + 2 * q + 1] = accg[q].y;
        }
    }

    __syncthreads();

    // coalesced geom writeback
    const int blockBase = blockIdx.x * BLOCK;
    int nvalid = N - blockBase;
    if (nvalid > BLOCK) nvalid = BLOCK;
    if (nvalid > 0) {
        float* gout = out + (size_t)N + (size_t)blockBase * 32;
        for (int i = tid; i < nvalid * 32; i += BLOCK) {
            const int row = i >> 5;
            const int col = i & 31;
            gout[i] = s_stage[row * 33 + col];
        }
    }
}

extern "C" void kernel_launch(void* const* d_in, const int* in_sizes, int n_in,
                              void* d_out, int out_size)
{
    const float* points = (const float*)d_in[0];
    const int*   iter   = (const int*)  d_in[1];
    const float* tables = (const float*)d_in[2];
    const float* shifts = (const float*)d_in[3];
    const float* w1 = (const float*)d_in[4];  const float* b1 = (const float*)d_in[5];
    const float* w2 = (const float*)d_in[6];  const float* b2 = (const float*)d_in[7];
    const float* w3 = (const float*)d_in[8];  const float* b3 = (const float*)d_in[9];
    const float* w4 = (const float*)d_in[10]; const float* b4 = (const float*)d_in[11];

    const int N = in_sizes[0] / 3;
    const int grid = (N + BLOCK - 1) / BLOCK;
    sdf_kernel<<<grid, BLOCK>>>(points, iter, tables, shifts,
                                w1, b1, w2, b2, w3, b3, w4, b4,
                                (float*)d_out, N);
}

// round 6
// speedup vs baseline: 1.0414x; 1.0083x over previous
#include <cuda_runtime.h>
#include <cstdint>
#include <math.h>

#define NLEV 24
#define CAPACITY (1u << 18)
#define BLOCK 128

union F2U { float2 f; unsigned long long u; };

// Packed dual-lane FMA: d = a*b + c on both f32 lanes (Blackwell FFMA2).
__device__ __forceinline__ float2 ffma2(float2 a, float2 b, float2 c) {
    F2U A, B, C, D;
    A.f = a; B.f = b; C.f = c;
    asm("fma.rn.f32x2 %0, %1, %2, %3;" : "=l"(D.u) : "l"(A.u), "l"(B.u), "l"(C.u));
    return D.f;
}
__device__ __forceinline__ float2 f2(float a, float b) { return make_float2(a, b); }

// Branch-free exact-GELU via Abramowitz-Stegun 7.1.26 erf (|err| <= ~1.5e-7 abs).
__device__ __forceinline__ float gelu_fast(float v) {
    const float z  = v * 0.70710678118654752f;
    const float az = fabsf(z);
    const float t  = __fdividef(1.0f, fmaf(0.3275911f, az, 1.0f));
    float p = fmaf(1.061405429f, t, -1.453152027f);
    p = fmaf(p, t, 1.421413741f);
    p = fmaf(p, t, -0.284496736f);
    p = fmaf(p, t, 0.254829592f);
    p *= t;
    const float e  = __expf(-az * az);
    const float er = copysignf(fmaf(-p, e, 1.0f), z);
    return 0.5f * v * (1.0f + er);
}

struct LevData {
    float2 g0, g1, g2, g3;   // gathered table entries (in flight)
    float  w0, w1, w2, w3;   // barycentric weights * c2f window
};

// Lattice math for one level; ISSUES the 4 hash gathers (consumed 2 levels later).
// Magic-constant rounding: exact round-half-even for |x| < 2^21, int via bit trick.
__device__ __forceinline__ LevData level_setup(
    int lev, float p0, float p1, float p2,
    const float* __restrict__ s_invsc,
    const float* __restrict__ s_shift,
    const float* __restrict__ s_win,
    const float2* __restrict__ tables)
{
    const float SF0 = 2.30940107675850341796875f;  // 4*sqrt(2/3)/sqrt(1*2)
    const float SF1 = 1.33333333333333333f;
    const float SF2 = 0.94280904158206336f;
    const float RM  = 12582912.0f;                 // 1.5 * 2^23
    const int   RI  = 0x4B400000;                  // bit pattern of RM

    const float inv  = s_invsc[lev];
    const float pos0 = fmaf(p0, inv, s_shift[lev * 3 + 0]);
    const float pos1 = fmaf(p1, inv, s_shift[lev * 3 + 1]);
    const float pos2 = fmaf(p2, inv, s_shift[lev * 3 + 2]);
    const float cf0 = pos0 * SF0, cf1 = pos1 * SF1, cf2 = pos2 * SF2;

    const float S2 = cf2;
    const float S1 = cf2 + cf1;
    const float S0 = S1 + cf0;

    float e[4];
    e[0] = S0;
    e[1] = S1 - cf0;
    e[2] = S2 - 2.0f * cf1;
    e[3] = -3.0f * cf2;

    // q = rint(e/4) + RM (magic); m = rint(e/4) as int; u = e/4 - rint(e/4)
    float q[4], u[4];
    int   m[4];
    #pragma unroll
    for (int i = 0; i < 4; i++) {
        q[i] = fmaf(e[i], 0.25f, RM);              // round-half-even into mantissa
        m[i] = __float_as_int(q[i]) - RI;          // integer rint(e/4)
        const float t = q[i] - RM;                 // rint(e/4) as float (exact)
        u[i] = fmaf(e[i], 0.25f, -t);              // delta (exact)
    }

    const int sumv = m[0] + m[1] + m[2] + m[3];

    // rank via 6 antisymmetric compares (stable argsort(argsort(-u)))
    const int t01 = (u[1] > u[0]);
    const int t02 = (u[2] > u[0]);
    const int t03 = (u[3] > u[0]);
    const int t12 = (u[2] > u[1]);
    const int t13 = (u[3] > u[1]);
    const int t23 = (u[3] > u[2]);

    int rk[4];
    rk[0] = sumv +     t01 + t02 + t03;
    rk[1] = sumv + 1 - t01 + t12 + t13;
    rk[2] = sumv + 2 - t02 - t12 + t23;
    rk[3] = sumv + 3 - t03 - t13 - t23;

    #pragma unroll
    for (int i = 0; i < 4; i++) {
        if (rk[i] < 0)      { rk[i] += 4; m[i] += 1; u[i] -= 1.0f; }
        else if (rk[i] > 3) { rk[i] -= 4; m[i] -= 1; u[i] += 1.0f; }
    }

    // barycentric weights
    float bq0 = 0.f, bq1 = 0.f, bq2 = 0.f, bq3 = 0.f, bq4 = 0.f;
    #pragma unroll
    for (int i = 0; i < 4; i++) {
        const int id = 3 - rk[i];
        const float dv = u[i];
        if (id == 0)      { bq0 += dv; bq1 -= dv; }
        else if (id == 1) { bq1 += dv; bq2 -= dv; }
        else if (id == 2) { bq2 += dv; bq3 -= dv; }
        else              { bq3 += dv; bq4 -= dv; }
    }
    const float wl = s_win[lev];
    LevData L;
    L.w0 = (bq0 + 1.0f + bq4) * wl;
    L.w1 = bq1 * wl;
    L.w2 = bq2 * wl;
    L.w3 = bq3 * wl;

    // vertex keys: key_i(k) = 4*m_i + ((k + rk_i) & 3) - rk_i
    const int b0 = 4 * m[0] - rk[0];
    const int b1 = 4 * m[1] - rk[1];
    const int b2 = 4 * m[2] - rk[2];
    const float2* tab = tables + (size_t)lev * CAPACITY;

    uint32_t idx[4];
    #pragma unroll
    for (int k = 0; k < 4; k++) {
        const uint32_t k0 = (uint32_t)(b0 + ((k + rk[0]) & 3));
        const uint32_t k1 = (uint32_t)(b1 + ((k + rk[1]) & 3));
        const uint32_t k2 = (uint32_t)(b2 + ((k + rk[2]) & 3));
        const uint32_t h = k0 ^ (k1 * 2654435761u) ^ (k2 * 805459861u);
        idx[k] = h & (CAPACITY - 1u);
    }
    L.g0 = __ldg(tab + idx[0]);
    L.g1 = __ldg(tab + idx[1]);
    L.g2 = __ldg(tab + idx[2]);
    L.g3 = __ldg(tab + idx[3]);
    return L;
}

__global__ __launch_bounds__(BLOCK, 4)
void sdf_kernel(const float* __restrict__ points,
                const int*   __restrict__ iter_nr,
                const float* __restrict__ tables,
                const float* __restrict__ shifts,
                const float* __restrict__ w1, const float* __restrict__ b1,
                const float* __restrict__ w2, const float* __restrict__ b2,
                const float* __restrict__ w3, const float* __restrict__ b3,
                const float* __restrict__ w4, const float* __restrict__ b4,
                float* __restrict__ out, int N)
{
    __shared__ float4 s_w1[51 * 8];
    __shared__ float4 s_w2[32 * 8];
    __shared__ float4 s_w3[32 * 8];
    __shared__ float4 s_w4g[32 * 8];
    __shared__ float  s_w4s[32];
    __shared__ float2 s_b1[16];
    __shared__ float2 s_b2[16];
    __shared__ float2 s_b3[16];
    __shared__ float  s_b4[33];
    __shared__ float  s_shift[NLEV * 3];
    __shared__ float  s_invsc[NLEV];
    __shared__ float  s_win[NLEV];
    __shared__ int    s_nlev;
    __shared__ float  s_stage[BLOCK * 33];

    const int tid = threadIdx.x;

    {
        const float4* g1 = (const float4*)w1;
        const float4* g2 = (const float4*)w2;
        const float4* g3 = (const float4*)w3;
        for (int i = tid; i < 51 * 8; i += BLOCK) s_w1[i] = g1[i];
        for (int i = tid; i < 32 * 8; i += BLOCK) s_w2[i] = g2[i];
        for (int i = tid; i < 32 * 8; i += BLOCK) s_w3[i] = g3[i];
    }
    {
        float* w4g = (float*)s_w4g;
        for (int i = tid; i < 32 * 33; i += BLOCK) {
            int r = i / 33, c = i - r * 33;
            float v = w4[i];
            if (c == 0) s_w4s[r] = v; else w4g[r * 32 + (c - 1)] = v;
        }
    }
    if (tid < 16) {
        s_b1[tid] = ((const float2*)b1)[tid];
        s_b2[tid] = ((const float2*)b2)[tid];
        s_b3[tid] = ((const float2*)b3)[tid];
    }
    if (tid < 33) s_b4[tid] = b4[tid];
    if (tid < NLEV * 3) s_shift[tid] = shifts[tid];
    if (tid < NLEV) {
        double step = -4.0 / 23.0;
        float sc = (float)pow(10.0, step * (double)tid);
        s_invsc[tid] = 1.0f / sc;
        float t = fminf(fmaxf((float)iter_nr[0] / 10000.0f, 0.0f), 1.0f);
        float alpha = (0.3f + 0.7f * t) * (float)NLEV;
        float x = fminf(fmaxf(alpha - (float)tid, 0.0f), 1.0f);
        s_win[tid] = 0.5f * (1.0f - cosf(3.14159265358979323846f * x));
        if (tid == 0) {
            int na = (int)ceilf(alpha);
            if (na > NLEV) na = NLEV;
            if (na < 0) na = 0;
            s_nlev = na;
        }
    }
    __syncthreads();

    const int n = blockIdx.x * BLOCK + tid;
    const bool active = (n < N);
    const int nlev = s_nlev;

    float  acc0;
    float2 accg[16];

    if (active) {
        const float p0 = __ldg(points + n * 3 + 0);
        const float p1 = __ldg(points + n * 3 + 1);
        const float p2 = __ldg(points + n * 3 + 2);
        const float2* tab2 = (const float2*)tables;

        // layer-1 accumulator seeded with bias + point*0.001 rows (48..50)
        float2 h1[16];
        {
            const float2 xa = f2(p0 * 0.001f, p0 * 0.001f);
            const float2 xb = f2(p1 * 0.001f, p1 * 0.001f);
            const float2 xc = f2(p2 * 0.001f, p2 * 0.001f);
            const float4* wa = s_w1 + 48 * 8;
            const float4* wb = s_w1 + 49 * 8;
            const float4* wc = s_w1 + 50 * 8;
            #pragma unroll
            for (int q = 0; q < 8; q++) {
                float4 A = wa[q], B = wb[q], C = wc[q];
                float2 v0 = ffma2(xa, f2(A.x, A.y), s_b1[2*q]);
                v0 = ffma2(xb, f2(B.x, B.y), v0);
                h1[2*q] = ffma2(xc, f2(C.x, C.y), v0);
                float2 v1 = ffma2(xa, f2(A.z, A.w), s_b1[2*q+1]);
                v1 = ffma2(xb, f2(B.z, B.w), v1);
                h1[2*q+1] = ffma2(xc, f2(C.z, C.w), v1);
            }
        }

        // ---- permutohedral encoding: depth-3 software pipeline ----
        LevData A, B, C;
        if (nlev > 0) A = level_setup(0, p0, p1, p2, s_invsc, s_shift, s_win, tab2);
        if (nlev > 1) B = level_setup(1, p0, p1, p2, s_invsc, s_shift, s_win, tab2);

        #pragma unroll 3
        for (int lev = 0; lev < nlev; ++lev) {
            if (lev + 2 < nlev)
                C = level_setup(lev + 2, p0, p1, p2, s_invsc, s_shift, s_win, tab2);

            // consume level lev (loads issued 2 iterations ago)
            float2 fe = ffma2(f2(A.w0, A.w0), A.g0, f2(0.0f, 0.0f));
            fe = ffma2(f2(A.w1, A.w1), A.g1, fe);
            fe = ffma2(f2(A.w2, A.w2), A.g2, fe);
            fe = ffma2(f2(A.w3, A.w3), A.g3, fe);

            const float2 f02 = f2(fe.x, fe.x);
            const float2 f12 = f2(fe.y, fe.y);

            const float4* ra = s_w1 + (2 * lev) * 8;
            #pragma unroll
            for (int q = 0; q < 8; q++) {
                float4 Aw = ra[q];
                float4 Bw = ra[q + 8];
                float2 v0 = ffma2(f02, f2(Aw.x, Aw.y), h1[2*q]);
                h1[2*q] = ffma2(f12, f2(Bw.x, Bw.y), v0);
                float2 v1 = ffma2(f02, f2(Aw.z, Aw.w), h1[2*q+1]);
                h1[2*q+1] = ffma2(f12, f2(Bw.z, Bw.w), v1);
            }

            A = B; B = C;
        }

        // ---- MLP ----
        #pragma unroll
        for (int q = 0; q < 16; q++) {
            h1[q].x = gelu_fast(h1[q].x);
            h1[q].y = gelu_fast(h1[q].y);
        }

        float2 h2[16];
        #pragma unroll
        for (int q = 0; q < 16; q++) h2[q] = s_b2[q];
        #pragma unroll
        for (int i = 0; i < 16; i++) {
            const float x0 = h1[i].x, x1 = h1[i].y;
            const float2 xa = f2(x0, x0);
            const float2 xb = f2(x1, x1);
            const float4* wr0 = s_w2 + (2 * i) * 8;
            const float4* wr1 = wr0 + 8;
            #pragma unroll
            for (int q = 0; q < 8; q++) {
                float4 Aw = wr0[q], Bw = wr1[q];
                float2 v0 = ffma2(xa, f2(Aw.x, Aw.y), h2[2*q]);
                h2[2*q] = ffma2(xb, f2(Bw.x, Bw.y), v0);
                float2 v1 = ffma2(xa, f2(Aw.z, Aw.w), h2[2*q+1]);
                h2[2*q+1] = ffma2(xb, f2(Bw.z, Bw.w), v1);
            }
        }
        #pragma unroll
        for (int q = 0; q < 16; q++) {
            h2[q].x = gelu_fast(h2[q].x);
            h2[q].y = gelu_fast(h2[q].y);
        }

        #pragma unroll
        for (int q = 0; q < 16; q++) h1[q] = s_b3[q];
        #pragma unroll
        for (int i = 0; i < 16; i++) {
            const float x0 = h2[i].x, x1 = h2[i].y;
            const float2 xa = f2(x0, x0);
            const float2 xb = f2(x1, x1);
            const float4* wr0 = s_w3 + (2 * i) * 8;
            const float4* wr1 = wr0 + 8;
            #pragma unroll
            for (int q = 0; q < 8; q++) {
                float4 Aw = wr0[q], Bw = wr1[q];
                float2 v0 = ffma2(xa, f2(Aw.x, Aw.y), h1[2*q]);
                h1[2*q] = ffma2(xb, f2(Bw.x, Bw.y), v0);
                float2 v1 = ffma2(xa, f2(Aw.z, Aw.w), h1[2*q+1]);
                h1[2*q+1] = ffma2(xb, f2(Bw.z, Bw.w), v1);
            }
        }
        #pragma unroll
        for (int q = 0; q < 16; q++) {
            h1[q].x = gelu_fast(h1[q].x);
            h1[q].y = gelu_fast(h1[q].y);
        }

        // layer 4
        acc0 = s_b4[0];
        #pragma unroll
        for (int q = 0; q < 16; q++)
            accg[q] = f2(s_b4[1 + 2 * q], s_b4[2 + 2 * q]);
        #pragma unroll
        for (int i = 0; i < 16; i++) {
            const float x0 = h1[i].x, x1 = h1[i].y;
            const float2 xa = f2(x0, x0);
            const float2 xb = f2(x1, x1);
            const float4* wr0 = s_w4g + (2 * i) * 8;
            const float4* wr1 = wr0 + 8;
            acc0 = fmaf(x0, s_w4s[2 * i], acc0);
            acc0 = fmaf(x1, s_w4s[2 * i + 1], acc0);
            #pragma unroll
            for (int q = 0; q < 8; q++) {
                float4 Aw = wr0[q], Bw = wr1[q];
                float2 v0 = ffma2(xa, f2(Aw.x, Aw.y), accg[2*q]);
                accg[2*q] = ffma2(xb, f2(Bw.x, Bw.y), v0);
                float2 v1 = ffma2(xa, f2(Aw.z, Aw.w), accg[2*q+1]);
                accg[2*q+1] = ffma2(xb, f2(Bw.z, Bw.w), v1);
            }
        }

        out[n] = acc0;

        #pragma unroll
        for (int q = 0; q < 16; q++) {
            s_stage[tid * 33 + 2 * q]     = accg[q].x;
            s_stage[tid * 33 + 2 * q + 1] = accg[q].y;
        }
    }

    __syncthreads();

    const int blockBase = blockIdx.x * BLOCK;
    int nvalid = N - blockBase;
    if (nvalid > BLOCK) nvalid = BLOCK;
    if (nvalid > 0) {
        float* gout = out + (size_t)N + (size_t)blockBase * 32;
        for (int i = tid; i < nvalid * 32; i += BLOCK) {
            const int row = i >> 5;
            const int col = i & 31;
            gout[i] = s_stage[row * 33 + col];
        }
    }
}

extern "C" void kernel_launch(void* const* d_in, const int* in_sizes, int n_in,
                              void* d_out, int out_size)
{
    const float* points = (const float*)d_in[0];
    const int*   iter   = (const int*)  d_in[1];
    const float* tables = (const float*)d_in[2];
    const float* shifts = (const float*)d_in[3];
    const float* w1 = (const float*)d_in[4];  const float* b1 = (const float*)d_in[5];
    const float* w2 = (const float*)d_in[6];  const float* b2 = (const float*)d_in[7];
    const float* w3 = (const float*)d_in[8];  const float* b3 = (const float*)d_in[9];
    const float* w4 = (const float*)d_in[10]; const float* b4 = (const float*)d_in[11];

    const int N = in_sizes[0] / 3;
    const int grid = (N + BLOCK - 1) / BLOCK;
    sdf_kernel<<<grid, BLOCK>>>(points, iter, tables, shifts,
                                w1, b1, w2, b2, w3, b3, w4, b4,
                                (float*)d_out, N);
}

// round 7
// speedup vs baseline: 1.0416x; 1.0002x over previous
#include <cuda_runtime.h>
#include <cstdint>
#include <math.h>

#define NLEV 24
#define CAPACITY (1u << 18)
#define BLOCK 128

union F2U { float2 f; unsigned long long u; };

// Packed dual-lane FMA / MUL (Blackwell f32x2 pipes).
__device__ __forceinline__ float2 ffma2(float2 a, float2 b, float2 c) {
    F2U A, B, C, D;
    A.f = a; B.f = b; C.f = c;
    asm("fma.rn.f32x2 %0, %1, %2, %3;" : "=l"(D.u) : "l"(A.u), "l"(B.u), "l"(C.u));
    return D.f;
}
__device__ __forceinline__ float2 mul2(float2 a, float2 b) {
    F2U A, B, D;
    A.f = a; B.f = b;
    asm("mul.rn.f32x2 %0, %1, %2;" : "=l"(D.u) : "l"(A.u), "l"(B.u));
    return D.f;
}
__device__ __forceinline__ float2 f2(float a, float b) { return make_float2(a, b); }

__device__ __forceinline__ float frcp(float x) {
    float r; asm("rcp.approx.f32 %0, %1;" : "=f"(r) : "f"(x)); return r;
}

// Packed-pair GELU, erf via A&S 7.1.25 (3-term, |err| <= 2.5e-5 abs).
__device__ __forceinline__ float2 gelu2(float2 v) {
    const float2 zc = f2(0.70710678118654752f, 0.70710678118654752f);
    float2 z  = mul2(v, zc);
    float2 az = f2(fabsf(z.x), fabsf(z.y));
    float2 den = ffma2(f2(0.47047f, 0.47047f), az, f2(1.0f, 1.0f));
    float2 t = f2(frcp(den.x), frcp(den.y));
    float2 p = ffma2(f2(0.7478556f, 0.7478556f), t, f2(-0.0958798f, -0.0958798f));
    p = ffma2(p, t, f2(0.3480242f, 0.3480242f));
    p = mul2(p, t);
    float2 zz = mul2(az, az);
    float2 e = f2(__expf(-zz.x), __expf(-zz.y));
    float2 pe = mul2(p, e);
    float2 er = f2(copysignf(1.0f - pe.x, z.x), copysignf(1.0f - pe.y, z.y));
    float2 hv = mul2(v, f2(0.5f, 0.5f));
    return ffma2(hv, er, hv);
}

struct LevData {
    float2 g0, g1, g2, g3;   // gathered table entries
    float  w0, w1, w2, w3;   // barycentric weights * c2f window
};

// Lattice math for one level; issues the 4 hash gathers.
__device__ __forceinline__ LevData level_setup(
    float inv, float sh0, float sh1, float sh2, float wl,
    float p0, float p1, float p2,
    const float2* __restrict__ tab)
{
    const float SF0 = 2.30940107675850341796875f;  // 4*sqrt(2/3)/sqrt(1*2)
    const float SF1 = 1.33333333333333333f;
    const float SF2 = 0.94280904158206336f;
    const float RM  = 12582912.0f;                 // 1.5 * 2^23
    const int   RI  = 0x4B400000;                  // bit pattern of RM

    const float cf0 = fmaf(p0, inv, sh0) * SF0;
    const float cf1 = fmaf(p1, inv, sh1) * SF1;
    const float cf2 = fmaf(p2, inv, sh2) * SF2;

    const float S2 = cf2;
    const float S1 = cf2 + cf1;
    const float S0 = S1 + cf0;

    float e[4];
    e[0] = S0;
    e[1] = S1 - cf0;
    e[2] = S2 - 2.0f * cf1;
    e[3] = -3.0f * cf2;

    float u[4];
    int   m[4];
    #pragma unroll
    for (int i = 0; i < 4; i++) {
        const float q = fmaf(e[i], 0.25f, RM);     // round-half-even into mantissa
        m[i] = __float_as_int(q) - RI;             // rint(e/4) as int
        const float t = q - RM;                    // rint(e/4) as float (exact)
        u[i] = fmaf(e[i], 0.25f, -t);              // delta (exact)
    }

    const int sumv = m[0] + m[1] + m[2] + m[3];

    // rank via 6 antisymmetric compares (stable argsort(argsort(-u)))
    const int t01 = (u[1] > u[0]);
    const int t02 = (u[2] > u[0]);
    const int t03 = (u[3] > u[0]);
    const int t12 = (u[2] > u[1]);
    const int t13 = (u[3] > u[1]);
    const int t23 = (u[3] > u[2]);

    int rk[4];
    rk[0] = sumv +     t01 + t02 + t03;
    rk[1] = sumv + 1 - t01 + t12 + t13;
    rk[2] = sumv + 2 - t02 - t12 + t23;
    rk[3] = sumv + 3 - t03 - t13 - t23;

    #pragma unroll
    for (int i = 0; i < 4; i++) {
        if (rk[i] < 0)      { rk[i] += 4; m[i] += 1; u[i] -= 1.0f; }
        else if (rk[i] > 3) { rk[i] -= 4; m[i] -= 1; u[i] += 1.0f; }
    }

    // barycentric weights
    float bq0 = 0.f, bq1 = 0.f, bq2 = 0.f, bq3 = 0.f, bq4 = 0.f;
    #pragma unroll
    for (int i = 0; i < 4; i++) {
        const int id = 3 - rk[i];
        const float dv = u[i];
        if (id == 0)      { bq0 += dv; bq1 -= dv; }
        else if (id == 1) { bq1 += dv; bq2 -= dv; }
        else if (id == 2) { bq2 += dv; bq3 -= dv; }
        else              { bq3 += dv; bq4 -= dv; }
    }
    LevData L;
    L.w0 = (bq0 + 1.0f + bq4) * wl;
    L.w1 = bq1 * wl;
    L.w2 = bq2 * wl;
    L.w3 = bq3 * wl;

    // vertex keys: key_i(k) = 4*m_i + ((k + rk_i) & 3) - rk_i
    const int b0 = 4 * m[0] - rk[0];
    const int b1 = 4 * m[1] - rk[1];
    const int b2 = 4 * m[2] - rk[2];

    uint32_t idx[4];
    #pragma unroll
    for (int k = 0; k < 4; k++) {
        const uint32_t k0 = (uint32_t)(b0 + ((k + rk[0]) & 3));
        const uint32_t k1 = (uint32_t)(b1 + ((k + rk[1]) & 3));
        const uint32_t k2 = (uint32_t)(b2 + ((k + rk[2]) & 3));
        const uint32_t h = k0 ^ (k1 * 2654435761u) ^ (k2 * 805459861u);
        idx[k] = h & (CAPACITY - 1u);
    }
    L.g0 = __ldg(tab + idx[0]);
    L.g1 = __ldg(tab + idx[1]);
    L.g2 = __ldg(tab + idx[2]);
    L.g3 = __ldg(tab + idx[3]);
    return L;
}

__global__ __launch_bounds__(BLOCK, 3)
void sdf_kernel(const float* __restrict__ points,
                const int*   __restrict__ iter_nr,
                const float* __restrict__ tables,
                const float* __restrict__ shifts,
                const float* __restrict__ w1, const float* __restrict__ b1,
                const float* __restrict__ w2, const float* __restrict__ b2,
                const float* __restrict__ w3, const float* __restrict__ b3,
                const float* __restrict__ w4, const float* __restrict__ b4,
                float* __restrict__ out, int N)
{
    __shared__ float4 s_w1[51 * 8];
    __shared__ float4 s_w2[32 * 8];
    __shared__ float4 s_w3[32 * 8];
    __shared__ float4 s_w4g[32 * 8];    // geom cols 1..32
    __shared__ float  s_w4s[32];        // sdf column 0
    __shared__ float2 s_b1[16];
    __shared__ float2 s_b2[16];
    __shared__ float2 s_b3[16];
    __shared__ float  s_b4[33];
    __shared__ float  s_shift[NLEV * 3];
    __shared__ float  s_invsc[NLEV];
    __shared__ float  s_win[NLEV];
    __shared__ int    s_nlev;

    const int tid = threadIdx.x;

    {
        const float4* g1 = (const float4*)w1;
        const float4* g2 = (const float4*)w2;
        const float4* g3 = (const float4*)w3;
        for (int i = tid; i < 51 * 8; i += BLOCK) s_w1[i] = g1[i];
        for (int i = tid; i < 32 * 8; i += BLOCK) s_w2[i] = g2[i];
        for (int i = tid; i < 32 * 8; i += BLOCK) s_w3[i] = g3[i];
    }
    {
        float* w4g = (float*)s_w4g;
        for (int i = tid; i < 32 * 33; i += BLOCK) {
            int r = i / 33, c = i - r * 33;
            float v = w4[i];
            if (c == 0) s_w4s[r] = v; else w4g[r * 32 + (c - 1)] = v;
        }
    }
    if (tid < 16) {
        s_b1[tid] = ((const float2*)b1)[tid];
        s_b2[tid] = ((const float2*)b2)[tid];
        s_b3[tid] = ((const float2*)b3)[tid];
    }
    if (tid < 33) s_b4[tid] = b4[tid];
    if (tid < NLEV * 3) s_shift[tid] = shifts[tid];
    if (tid < NLEV) {
        double step = -4.0 / 23.0;
        float sc = (float)pow(10.0, step * (double)tid);
        s_invsc[tid] = 1.0f / sc;
        float t = fminf(fmaxf((float)iter_nr[0] / 10000.0f, 0.0f), 1.0f);
        float alpha = (0.3f + 0.7f * t) * (float)NLEV;
        float x = fminf(fmaxf(alpha - (float)tid, 0.0f), 1.0f);
        s_win[tid] = 0.5f * (1.0f - cosf(3.14159265358979323846f * x));
        if (tid == 0) {
            int na = (int)ceilf(alpha);
            if (na > NLEV) na = NLEV;
            if (na < 0) na = 0;
            s_nlev = na;
        }
    }
    __syncthreads();

    const int base = blockIdx.x * (BLOCK * 2);
    const int n0 = base + tid;
    const int n1 = base + BLOCK + tid;
    const bool a0 = (n0 < N);
    const bool a1 = (n1 < N);
    const int m0 = a0 ? n0 : (N - 1);
    const int m1 = a1 ? n1 : (N - 1);
    const int nlev = s_nlev;

    const float pA0 = __ldg(points + m0 * 3 + 0);
    const float pA1 = __ldg(points + m0 * 3 + 1);
    const float pA2 = __ldg(points + m0 * 3 + 2);
    const float pB0 = __ldg(points + m1 * 3 + 0);
    const float pB1 = __ldg(points + m1 * 3 + 1);
    const float pB2 = __ldg(points + m1 * 3 + 2);
    const float2* tab2 = (const float2*)tables;

    // ---- layer-1 accumulators seeded with bias + point*0.001 rows (48..50)
    float2 h1a[16], h1b[16];
    {
        const float2 xaA = f2(pA0 * 0.001f, pA0 * 0.001f);
        const float2 xbA = f2(pA1 * 0.001f, pA1 * 0.001f);
        const float2 xcA = f2(pA2 * 0.001f, pA2 * 0.001f);
        const float2 xaB = f2(pB0 * 0.001f, pB0 * 0.001f);
        const float2 xbB = f2(pB1 * 0.001f, pB1 * 0.001f);
        const float2 xcB = f2(pB2 * 0.001f, pB2 * 0.001f);
        const float4* wa = s_w1 + 48 * 8;
        const float4* wb = s_w1 + 49 * 8;
        const float4* wc = s_w1 + 50 * 8;
        #pragma unroll
        for (int q = 0; q < 8; q++) {
            float4 A = wa[q], B = wb[q], C = wc[q];
            float2 A0 = f2(A.x, A.y), A1 = f2(A.z, A.w);
            float2 B0 = f2(B.x, B.y), B1 = f2(B.z, B.w);
            float2 C0 = f2(C.x, C.y), C1 = f2(C.z, C.w);
            float2 v;
            v = ffma2(xaA, A0, s_b1[2*q]); v = ffma2(xbA, B0, v); h1a[2*q]   = ffma2(xcA, C0, v);
            v = ffma2(xaA, A1, s_b1[2*q+1]); v = ffma2(xbA, B1, v); h1a[2*q+1] = ffma2(xcA, C1, v);
            v = ffma2(xaB, A0, s_b1[2*q]); v = ffma2(xbB, B0, v); h1b[2*q]   = ffma2(xcB, C0, v);
            v = ffma2(xaB, A1, s_b1[2*q+1]); v = ffma2(xbB, B1, v); h1b[2*q+1] = ffma2(xcB, C1, v);
        }
    }

    // ---- permutohedral encoding (both points share the w1 row loads) ----
    #pragma unroll 1
    for (int lev = 0; lev < nlev; ++lev) {
        const float inv = s_invsc[lev];
        const float sh0 = s_shift[lev * 3 + 0];
        const float sh1 = s_shift[lev * 3 + 1];
        const float sh2 = s_shift[lev * 3 + 2];
        const float wl  = s_win[lev];
        const float2* tab = tab2 + (size_t)lev * CAPACITY;

        LevData LA = level_setup(inv, sh0, sh1, sh2, wl, pA0, pA1, pA2, tab);
        LevData LB = level_setup(inv, sh0, sh1, sh2, wl, pB0, pB1, pB2, tab);

        float2 feA = ffma2(f2(LA.w0, LA.w0), LA.g0, f2(0.f, 0.f));
        feA = ffma2(f2(LA.w1, LA.w1), LA.g1, feA);
        feA = ffma2(f2(LA.w2, LA.w2), LA.g2, feA);
        feA = ffma2(f2(LA.w3, LA.w3), LA.g3, feA);
        float2 feB = ffma2(f2(LB.w0, LB.w0), LB.g0, f2(0.f, 0.f));
        feB = ffma2(f2(LB.w1, LB.w1), LB.g1, feB);
        feB = ffma2(f2(LB.w2, LB.w2), LB.g2, feB);
        feB = ffma2(f2(LB.w3, LB.w3), LB.g3, feB);

        const float2 f0A = f2(feA.x, feA.x), f1A = f2(feA.y, feA.y);
        const float2 f0B = f2(feB.x, feB.x), f1B = f2(feB.y, feB.y);

        const float4* ra = s_w1 + (2 * lev) * 8;
        #pragma unroll
        for (int q = 0; q < 8; q++) {
            float4 Aw = ra[q];       // row 2*lev
            float4 Bw = ra[q + 8];   // row 2*lev+1
            float2 A0 = f2(Aw.x, Aw.y), A1 = f2(Aw.z, Aw.w);
            float2 B0 = f2(Bw.x, Bw.y), B1 = f2(Bw.z, Bw.w);
            h1a[2*q]   = ffma2(f1A, B0, ffma2(f0A, A0, h1a[2*q]));
            h1a[2*q+1] = ffma2(f1A, B1, ffma2(f0A, A1, h1a[2*q+1]));
            h1b[2*q]   = ffma2(f1B, B0, ffma2(f0B, A0, h1b[2*q]));
            h1b[2*q+1] = ffma2(f1B, B1, ffma2(f0B, A1, h1b[2*q+1]));
        }
    }

    // ---- MLP ----
    #pragma unroll
    for (int q = 0; q < 16; q++) { h1a[q] = gelu2(h1a[q]); h1b[q] = gelu2(h1b[q]); }

    float2 h2a[16], h2b[16];
    #pragma unroll
    for (int q = 0; q < 16; q++) { h2a[q] = s_b2[q]; h2b[q] = s_b2[q]; }
    #pragma unroll
    for (int i = 0; i < 16; i++) {
        const float2 xaA = f2(h1a[i].x, h1a[i].x), xbA = f2(h1a[i].y, h1a[i].y);
        const float2 xaB = f2(h1b[i].x, h1b[i].x), xbB = f2(h1b[i].y, h1b[i].y);
        const float4* wr0 = s_w2 + (2 * i) * 8;
        const float4* wr1 = wr0 + 8;
        #pragma unroll
        for (int q = 0; q < 8; q++) {
            float4 Aw = wr0[q], Bw = wr1[q];
            float2 A0 = f2(Aw.x, Aw.y), A1 = f2(Aw.z, Aw.w);
            float2 B0 = f2(Bw.x, Bw.y), B1 = f2(Bw.z, Bw.w);
            h2a[2*q]   = ffma2(xbA, B0, ffma2(xaA, A0, h2a[2*q]));
            h2a[2*q+1] = ffma2(xbA, B1, ffma2(xaA, A1, h2a[2*q+1]));
            h2b[2*q]   = ffma2(xbB, B0, ffma2(xaB, A0, h2b[2*q]));
            h2b[2*q+1] = ffma2(xbB, B1, ffma2(xaB, A1, h2b[2*q+1]));
        }
    }
    #pragma unroll
    for (int q = 0; q < 16; q++) { h2a[q] = gelu2(h2a[q]); h2b[q] = gelu2(h2b[q]); }

    // layer 3 back into h1
    #pragma unroll
    for (int q = 0; q < 16; q++) { h1a[q] = s_b3[q]; h1b[q] = s_b3[q]; }
    #pragma unroll
    for (int i = 0; i < 16; i++) {
        const float2 xaA = f2(h2a[i].x, h2a[i].x), xbA = f2(h2a[i].y, h2a[i].y);
        const float2 xaB = f2(h2b[i].x, h2b[i].x), xbB = f2(h2b[i].y, h2b[i].y);
        const float4* wr0 = s_w3 + (2 * i) * 8;
        const float4* wr1 = wr0 + 8;
        #pragma unroll
        for (int q = 0; q < 8; q++) {
            float4 Aw = wr0[q], Bw = wr1[q];
            float2 A0 = f2(Aw.x, Aw.y), A1 = f2(Aw.z, Aw.w);
            float2 B0 = f2(Bw.x, Bw.y), B1 = f2(Bw.z, Bw.w);
            h1a[2*q]   = ffma2(xbA, B0, ffma2(xaA, A0, h1a[2*q]));
            h1a[2*q+1] = ffma2(xbA, B1, ffma2(xaA, A1, h1a[2*q+1]));
            h1b[2*q]   = ffma2(xbB, B0, ffma2(xaB, A0, h1b[2*q]));
            h1b[2*q+1] = ffma2(xbB, B1, ffma2(xaB, A1, h1b[2*q+1]));
        }
    }
    #pragma unroll
    for (int q = 0; q < 16; q++) { h1a[q] = gelu2(h1a[q]); h1b[q] = gelu2(h1b[q]); }

    // layer 4 (shared weight loads; h2 arrays reused as geom accumulators)
    float accsA = s_b4[0], accsB = s_b4[0];
    #pragma unroll
    for (int q = 0; q < 16; q++) {
        float2 bb = f2(s_b4[1 + 2 * q], s_b4[2 + 2 * q]);
        h2a[q] = bb; h2b[q] = bb;
    }
    #pragma unroll
    for (int i = 0; i < 16; i++) {
        const float x0A = h1a[i].x, x1A = h1a[i].y;
        const float x0B = h1b[i].x, x1B = h1b[i].y;
        const float2 xaA = f2(x0A, x0A), xbA = f2(x1A, x1A);
        const float2 xaB = f2(x0B, x0B), xbB = f2(x1B, x1B);
        const float4* wr0 = s_w4g + (2 * i) * 8;
        const float4* wr1 = wr0 + 8;
        const float ws0 = s_w4s[2 * i], ws1 = s_w4s[2 * i + 1];
        accsA = fmaf(x1A, ws1, fmaf(x0A, ws0, accsA));
        accsB = fmaf(x1B, ws1, fmaf(x0B, ws0, accsB));
        #pragma unroll
        for (int q = 0; q < 8; q++) {
            float4 Aw = wr0[q], Bw = wr1[q];
            float2 A0 = f2(Aw.x, Aw.y), A1 = f2(Aw.z, Aw.w);
            float2 B0 = f2(Bw.x, Bw.y), B1 = f2(Bw.z, Bw.w);
            h2a[2*q]   = ffma2(xbA, B0, ffma2(xaA, A0, h2a[2*q]));
            h2a[2*q+1] = ffma2(xbA, B1, ffma2(xaA, A1, h2a[2*q+1]));
            h2b[2*q]   = ffma2(xbB, B0, ffma2(xaB, A0, h2b[2*q]));
            h2b[2*q+1] = ffma2(xbB, B1, ffma2(xaB, A1, h2b[2*q+1]));
        }
    }

    // ---- outputs: sdf scalar + direct STG.128 geom rows ----
    if (a0) {
        out[n0] = accsA;
        float4* gout = (float4*)(out + (size_t)N + (size_t)n0 * 32);
        #pragma unroll
        for (int q = 0; q < 8; q++) {
            float4 o;
            o.x = h2a[2*q].x;   o.y = h2a[2*q].y;
            o.z = h2a[2*q+1].x; o.w = h2a[2*q+1].y;
            gout[q] = o;
        }
    }
    if (a1) {
        out[n1] = accsB;
        float4* gout = (float4*)(out + (size_t)N + (size_t)n1 * 32);
        #pragma unroll
        for (int q = 0; q < 8; q++) {
            float4 o;
            o.x = h2b[2*q].x;   o.y = h2b[2*q].y;
            o.z = h2b[2*q+1].x; o.w = h2b[2*q+1].y;
            gout[q] = o;
        }
    }
}

extern "C" void kernel_launch(void* const* d_in, const int* in_sizes, int n_in,
                              void* d_out, int out_size)
{
    const float* points = (const float*)d_in[0];
    const int*   iter   = (const int*)  d_in[1];
    const float* tables = (const float*)d_in[2];
    const float* shifts = (const float*)d_in[3];
    const float* w1 = (const float*)d_in[4];  const float* b1 = (const float*)d_in[5];
    const float* w2 = (const float*)d_in[6];  const float* b2 = (const float*)d_in[7];
    const float* w3 = (const float*)d_in[8];  const float* b3 = (const float*)d_in[9];
    const float* w4 = (const float*)d_in[10]; const float* b4 = (const float*)d_in[11];

    const int N = in_sizes[0] / 3;
    const int grid = (N + BLOCK * 2 - 1) / (BLOCK * 2);
    sdf_kernel<<<grid, BLOCK>>>(points, iter, tables, shifts,
                                w1, b1, w2, b2, w3, b3, w4, b4,
                                (float*)d_out, N);
}

// round 8
// speedup vs baseline: 1.2761x; 1.2251x over previous
#include <cuda_runtime.h>
#include <cstdint>
#include <math.h>

#define NLEV 24
#define CAPACITY (1u << 18)
#define MAXN 262144

// 48 feature rows, transposed layout [2*NLEV][MAXN] for coalesced access.
__device__ float g_enc[2 * NLEV * MAXN];

union F2U { float2 f; unsigned long long u; };

// Packed dual-lane FMA (Blackwell FFMA2 via PTX f32x2).
__device__ __forceinline__ float2 ffma2(float2 a, float2 b, float2 c) {
    F2U A, B, C, D;
    A.f = a; B.f = b; C.f = c;
    asm("fma.rn.f32x2 %0, %1, %2, %3;" : "=l"(D.u) : "l"(A.u), "l"(B.u), "l"(C.u));
    return D.f;
}
__device__ __forceinline__ float2 f2(float a, float b) { return make_float2(a, b); }

// Branch-free exact-GELU via Abramowitz-Stegun 7.1.26 erf (|err| <= ~1.5e-7 abs).
__device__ __forceinline__ float gelu_fast(float v) {
    const float z  = v * 0.70710678118654752f;
    const float az = fabsf(z);
    const float t  = __fdividef(1.0f, fmaf(0.3275911f, az, 1.0f));
    float p = fmaf(1.061405429f, t, -1.453152027f);
    p = fmaf(p, t, 1.421413741f);
    p = fmaf(p, t, -0.284496736f);
    p = fmaf(p, t, 0.254829592f);
    p *= t;
    const float e  = __expf(-az * az);
    const float er = copysignf(fmaf(-p, e, 1.0f), z);
    return 0.5f * v * (1.0f + er);
}

// ======================= K1: permutohedral encoding =======================

__global__ __launch_bounds__(256, 4)
void enc_kernel(const float* __restrict__ points,
                const int*   __restrict__ iter_nr,
                const float* __restrict__ tables,
                const float* __restrict__ shifts,
                int N)
{
    __shared__ float s_shift[NLEV * 3];
    __shared__ float s_invsc[NLEV];
    __shared__ float s_win[NLEV];
    __shared__ int   s_nlev;

    const int tid = threadIdx.x;
    if (tid < NLEV * 3) s_shift[tid] = shifts[tid];
    if (tid < NLEV) {
        // SCALES = geomspace(1, 1e-4, 24) = 10^(i * (-4/23)) in float64 -> f32
        double step = -4.0 / 23.0;
        float sc = (float)pow(10.0, step * (double)tid);
        s_invsc[tid] = 1.0f / sc;
        float t = fminf(fmaxf((float)iter_nr[0] / 10000.0f, 0.0f), 1.0f);
        float alpha = (0.3f + 0.7f * t) * (float)NLEV;
        float x = fminf(fmaxf(alpha - (float)tid, 0.0f), 1.0f);
        s_win[tid] = 0.5f * (1.0f - cosf(3.14159265358979323846f * x));
        if (tid == 0) {
            int na = (int)ceilf(alpha);
            if (na > NLEV) na = NLEV;
            if (na < 0) na = 0;
            s_nlev = na;
        }
    }
    __syncthreads();

    const int n = blockIdx.x * 256 + tid;
    if (n >= N) return;
    const int nlev = s_nlev;

    const float p0 = __ldg(points + n * 3 + 0);
    const float p1 = __ldg(points + n * 3 + 1);
    const float p2 = __ldg(points + n * 3 + 2);
    const float2* tab2 = (const float2*)tables;

    const float SF0 = 2.30940107675850341796875f;  // 4*sqrt(2/3)/sqrt(1*2)
    const float SF1 = 1.33333333333333333f;
    const float SF2 = 0.94280904158206336f;
    const float RM  = 12582912.0f;                 // 1.5 * 2^23
    const int   RI  = 0x4B400000;                  // bit pattern of RM

    #pragma unroll 1
    for (int lev = 0; lev < nlev; ++lev) {
        const float inv = s_invsc[lev];
        const float cf0 = fmaf(p0, inv, s_shift[lev * 3 + 0]) * SF0;
        const float cf1 = fmaf(p1, inv, s_shift[lev * 3 + 1]) * SF1;
        const float cf2 = fmaf(p2, inv, s_shift[lev * 3 + 2]) * SF2;

        const float S2 = cf2;
        const float S1 = cf2 + cf1;
        const float S0 = S1 + cf0;

        float e[4];
        e[0] = S0;
        e[1] = S1 - cf0;
        e[2] = S2 - 2.0f * cf1;
        e[3] = -3.0f * cf2;

        float u[4];
        int   m[4];
        #pragma unroll
        for (int i = 0; i < 4; i++) {
            const float q = fmaf(e[i], 0.25f, RM);     // round-half-even
            m[i] = __float_as_int(q) - RI;             // rint(e/4) as int
            const float t = q - RM;                    // rint(e/4) float (exact)
            u[i] = fmaf(e[i], 0.25f, -t);              // delta (exact)
        }

        const int sumv = m[0] + m[1] + m[2] + m[3];

        // rank via 6 antisymmetric compares (stable argsort(argsort(-u)))
        const int t01 = (u[1] > u[0]);
        const int t02 = (u[2] > u[0]);
        const int t03 = (u[3] > u[0]);
        const int t12 = (u[2] > u[1]);
        const int t13 = (u[3] > u[1]);
        const int t23 = (u[3] > u[2]);

        int rk[4];
        rk[0] = sumv +     t01 + t02 + t03;
        rk[1] = sumv + 1 - t01 + t12 + t13;
        rk[2] = sumv + 2 - t02 - t12 + t23;
        rk[3] = sumv + 3 - t03 - t13 - t23;

        #pragma unroll
        for (int i = 0; i < 4; i++) {
            if (rk[i] < 0)      { rk[i] += 4; m[i] += 1; u[i] -= 1.0f; }
            else if (rk[i] > 3) { rk[i] -= 4; m[i] -= 1; u[i] += 1.0f; }
        }

        // barycentric weights
        float bq0 = 0.f, bq1 = 0.f, bq2 = 0.f, bq3 = 0.f, bq4 = 0.f;
        #pragma unroll
        for (int i = 0; i < 4; i++) {
            const int id = 3 - rk[i];
            const float dv = u[i];
            if (id == 0)      { bq0 += dv; bq1 -= dv; }
            else if (id == 1) { bq1 += dv; bq2 -= dv; }
            else if (id == 2) { bq2 += dv; bq3 -= dv; }
            else              { bq3 += dv; bq4 -= dv; }
        }
        const float wl = s_win[lev];
        float w0 = (bq0 + 1.0f + bq4) * wl;
        float w1 = bq1 * wl;
        float w2 = bq2 * wl;
        float w3 = bq3 * wl;

        // vertex keys: key_i(k) = 4*m_i + ((k + rk_i) & 3) - rk_i
        const int b0 = 4 * m[0] - rk[0];
        const int b1 = 4 * m[1] - rk[1];
        const int b2 = 4 * m[2] - rk[2];
        const float2* tab = tab2 + (size_t)lev * CAPACITY;

        uint32_t idx[4];
        #pragma unroll
        for (int k = 0; k < 4; k++) {
            const uint32_t k0 = (uint32_t)(b0 + ((k + rk[0]) & 3));
            const uint32_t k1 = (uint32_t)(b1 + ((k + rk[1]) & 3));
            const uint32_t k2 = (uint32_t)(b2 + ((k + rk[2]) & 3));
            const uint32_t h = k0 ^ (k1 * 2654435761u) ^ (k2 * 805459861u);
            idx[k] = h & (CAPACITY - 1u);
        }
        const float2 g0 = __ldg(tab + idx[0]);
        const float2 g1 = __ldg(tab + idx[1]);
        const float2 g2 = __ldg(tab + idx[2]);
        const float2 g3 = __ldg(tab + idx[3]);

        float f0 = g0.x * w0, fy = g0.y * w0;
        f0 = fmaf(g1.x, w1, f0); fy = fmaf(g1.y, w1, fy);
        f0 = fmaf(g2.x, w2, f0); fy = fmaf(g2.y, w2, fy);
        f0 = fmaf(g3.x, w3, f0); fy = fmaf(g3.y, w3, fy);

        // transposed, coalesced stores
        g_enc[(size_t)(2 * lev) * MAXN + n]     = f0;
        g_enc[(size_t)(2 * lev + 1) * MAXN + n] = fy;
    }
}

// ============================ K2: the MLP ============================

__global__ __launch_bounds__(128, 5)
void mlp_kernel(const float* __restrict__ points,
                const int*   __restrict__ iter_nr,
                const float* __restrict__ w1, const float* __restrict__ b1,
                const float* __restrict__ w2, const float* __restrict__ b2,
                const float* __restrict__ w3, const float* __restrict__ b3,
                const float* __restrict__ w4, const float* __restrict__ b4,
                float* __restrict__ out, int N)
{
    __shared__ float4 s_w1[51 * 8];
    __shared__ float4 s_w2[32 * 8];
    __shared__ float4 s_w3[32 * 8];
    __shared__ float4 s_w4g[32 * 8];    // geom cols 1..32
    __shared__ float  s_w4s[32];        // sdf column 0
    __shared__ float2 s_b1[16];
    __shared__ float2 s_b2[16];
    __shared__ float2 s_b3[16];
    __shared__ float  s_b4[33];
    __shared__ int    s_nlev;

    const int tid = threadIdx.x;

    {
        const float4* g1 = (const float4*)w1;
        const float4* g2 = (const float4*)w2;
        const float4* g3 = (const float4*)w3;
        for (int i = tid; i < 51 * 8; i += 128) s_w1[i] = g1[i];
        for (int i = tid; i < 32 * 8; i += 128) s_w2[i] = g2[i];
        for (int i = tid; i < 32 * 8; i += 128) s_w3[i] = g3[i];
    }
    {
        float* w4g = (float*)s_w4g;
        for (int i = tid; i < 32 * 33; i += 128) {
            int r = i / 33, c = i - r * 33;
            float v = w4[i];
            if (c == 0) s_w4s[r] = v; else w4g[r * 32 + (c - 1)] = v;
        }
    }
    if (tid < 16) {
        s_b1[tid] = ((const float2*)b1)[tid];
        s_b2[tid] = ((const float2*)b2)[tid];
        s_b3[tid] = ((const float2*)b3)[tid];
    }
    if (tid < 33) s_b4[tid] = b4[tid];
    if (tid == 0) {
        float t = fminf(fmaxf((float)iter_nr[0] / 10000.0f, 0.0f), 1.0f);
        float alpha = (0.3f + 0.7f * t) * (float)NLEV;
        int na = (int)ceilf(alpha);
        if (na > NLEV) na = NLEV;
        if (na < 0) na = 0;
        s_nlev = na;
    }
    __syncthreads();

    const int n = blockIdx.x * 128 + tid;
    if (n >= N) return;
    const int nlev = s_nlev;

    const float p0 = __ldg(points + n * 3 + 0);
    const float p1 = __ldg(points + n * 3 + 1);
    const float p2 = __ldg(points + n * 3 + 2);

    // ---- layer-1 accumulator, seeded with bias + point*0.001 rows (48..50)
    float2 h1[16];
    {
        const float2 xa = f2(p0 * 0.001f, p0 * 0.001f);
        const float2 xb = f2(p1 * 0.001f, p1 * 0.001f);
        const float2 xc = f2(p2 * 0.001f, p2 * 0.001f);
        const float4* wa = s_w1 + 48 * 8;
        const float4* wb = s_w1 + 49 * 8;
        const float4* wc = s_w1 + 50 * 8;
        #pragma unroll
        for (int q = 0; q < 8; q++) {
            float4 A = wa[q], B = wb[q], C = wc[q];
            float2 v0 = ffma2(xa, f2(A.x, A.y), s_b1[2*q]);
            v0 = ffma2(xb, f2(B.x, B.y), v0);
            h1[2*q] = ffma2(xc, f2(C.x, C.y), v0);
            float2 v1 = ffma2(xa, f2(A.z, A.w), s_b1[2*q+1]);
            v1 = ffma2(xb, f2(B.z, B.w), v1);
            h1[2*q+1] = ffma2(xc, f2(C.z, C.w), v1);
        }
    }

    // ---- fold encoded features (L2-hot coalesced reads) into layer 1 ----
    #pragma unroll 1
    for (int lev = 0; lev < nlev; ++lev) {
        const float fx = g_enc[(size_t)(2 * lev) * MAXN + n];
        const float fy = g_enc[(size_t)(2 * lev + 1) * MAXN + n];
        const float2 f0 = f2(fx, fx);
        const float2 f1 = f2(fy, fy);
        const float4* ra = s_w1 + (2 * lev) * 8;
        #pragma unroll
        for (int q = 0; q < 8; q++) {
            float4 A = ra[q];       // row 2*lev
            float4 B = ra[q + 8];   // row 2*lev+1
            float2 v0 = ffma2(f0, f2(A.x, A.y), h1[2*q]);
            h1[2*q] = ffma2(f1, f2(B.x, B.y), v0);
            float2 v1 = ffma2(f0, f2(A.z, A.w), h1[2*q+1]);
            h1[2*q+1] = ffma2(f1, f2(B.z, B.w), v1);
        }
    }

    // ---- layers 2..4 ----
    #pragma unroll
    for (int q = 0; q < 16; q++) {
        h1[q].x = gelu_fast(h1[q].x);
        h1[q].y = gelu_fast(h1[q].y);
    }

    float2 h2[16];
    #pragma unroll
    for (int q = 0; q < 16; q++) h2[q] = s_b2[q];
    #pragma unroll
    for (int i = 0; i < 16; i++) {
        const float2 xa = f2(h1[i].x, h1[i].x);
        const float2 xb = f2(h1[i].y, h1[i].y);
        const float4* wr0 = s_w2 + (2 * i) * 8;
        const float4* wr1 = wr0 + 8;
        #pragma unroll
        for (int q = 0; q < 8; q++) {
            float4 A = wr0[q], B = wr1[q];
            float2 v0 = ffma2(xa, f2(A.x, A.y), h2[2*q]);
            h2[2*q] = ffma2(xb, f2(B.x, B.y), v0);
            float2 v1 = ffma2(xa, f2(A.z, A.w), h2[2*q+1]);
            h2[2*q+1] = ffma2(xb, f2(B.z, B.w), v1);
        }
    }
    #pragma unroll
    for (int q = 0; q < 16; q++) {
        h2[q].x = gelu_fast(h2[q].x);
        h2[q].y = gelu_fast(h2[q].y);
    }

    #pragma unroll
    for (int q = 0; q < 16; q++) h1[q] = s_b3[q];
    #pragma unroll
    for (int i = 0; i < 16; i++) {
        const float2 xa = f2(h2[i].x, h2[i].x);
        const float2 xb = f2(h2[i].y, h2[i].y);
        const float4* wr0 = s_w3 + (2 * i) * 8;
        const float4* wr1 = wr0 + 8;
        #pragma unroll
        for (int q = 0; q < 8; q++) {
            float4 A = wr0[q], B = wr1[q];
            float2 v0 = ffma2(xa, f2(A.x, A.y), h1[2*q]);
            h1[2*q] = ffma2(xb, f2(B.x, B.y), v0);
            float2 v1 = ffma2(xa, f2(A.z, A.w), h1[2*q+1]);
            h1[2*q+1] = ffma2(xb, f2(B.z, B.w), v1);
        }
    }
    #pragma unroll
    for (int q = 0; q < 16; q++) {
        h1[q].x = gelu_fast(h1[q].x);
        h1[q].y = gelu_fast(h1[q].y);
    }

    // layer 4 (h2 reused as geom accumulator)
    float acc0 = s_b4[0];
    #pragma unroll
    for (int q = 0; q < 16; q++)
        h2[q] = f2(s_b4[1 + 2 * q], s_b4[2 + 2 * q]);
    #pragma unroll
    for (int i = 0; i < 16; i++) {
        const float x0 = h1[i].x, x1 = h1[i].y;
        const float2 xa = f2(x0, x0);
        const float2 xb = f2(x1, x1);
        const float4* wr0 = s_w4g + (2 * i) * 8;
        const float4* wr1 = wr0 + 8;
        acc0 = fmaf(x1, s_w4s[2 * i + 1], fmaf(x0, s_w4s[2 * i], acc0));
        #pragma unroll
        for (int q = 0; q < 8; q++) {
            float4 A = wr0[q], B = wr1[q];
            float2 v0 = ffma2(xa, f2(A.x, A.y), h2[2*q]);
            h2[2*q] = ffma2(xb, f2(B.x, B.y), v0);
            float2 v1 = ffma2(xa, f2(A.z, A.w), h2[2*q+1]);
            h2[2*q+1] = ffma2(xb, f2(B.z, B.w), v1);
        }
    }

    out[n] = acc0;
    float4* gout = (float4*)(out + (size_t)N + (size_t)n * 32);
    #pragma unroll
    for (int q = 0; q < 8; q++) {
        float4 o;
        o.x = h2[2*q].x;   o.y = h2[2*q].y;
        o.z = h2[2*q+1].x; o.w = h2[2*q+1].y;
        gout[q] = o;
    }
}

extern "C" void kernel_launch(void* const* d_in, const int* in_sizes, int n_in,
                              void* d_out, int out_size)
{
    const float* points = (const float*)d_in[0];
    const int*   iter   = (const int*)  d_in[1];
    const float* tables = (const float*)d_in[2];
    const float* shifts = (const float*)d_in[3];
    const float* w1 = (const float*)d_in[4];  const float* b1 = (const float*)d_in[5];
    const float* w2 = (const float*)d_in[6];  const float* b2 = (const float*)d_in[7];
    const float* w3 = (const float*)d_in[8];  const float* b3 = (const float*)d_in[9];
    const float* w4 = (const float*)d_in[10]; const float* b4 = (const float*)d_in[11];

    const int N = in_sizes[0] / 3;

    const int grid1 = (N + 255) / 256;
    enc_kernel<<<grid1, 256>>>(points, iter, tables, shifts, N);

    const int grid2 = (N + 127) / 128;
    mlp_kernel<<<grid2, 128>>>(points, iter,
                               w1, b1, w2, b2, w3, b3, w4, b4,
                               (float*)d_out, N);
}